// round 12
// baseline (speedup 1.0000x reference)
#include <cuda_runtime.h>
#include <cuda_fp16.h>
#include <cstdint>

#define S_LEN 2048
#define NHEAD 16
#define HDIM  64
#define NREL  65
#define NBH   32
#define NM    4096
#define ND    1024

// ---------------- static device scratch ----------------
__device__ __half g_xhi[NM * ND];
__device__ __half g_Whi[4 * ND * ND], g_Wlo[4 * ND * ND];
__device__ __half g_Qh[NBH * S_LEN * HDIM];
__device__ __half g_KhG[NBH * S_LEN * HDIM];
__device__ __half g_VhG[NBH * S_LEN * HDIM];
__device__ __half g_Ohi[NM * ND], g_Olo[NM * ND];

// ---------------- helpers ----------------
__device__ __forceinline__ uint32_t s2u(const void* p) {
    return (uint32_t)__cvta_generic_to_shared(p);
}
__device__ __forceinline__ void cpa16(uint32_t d, const void* s) {
    asm volatile("cp.async.cg.shared.global [%0], [%1], 16;\n" :: "r"(d), "l"(s));
}
#define CP_COMMIT() asm volatile("cp.async.commit_group;\n" ::)
#define CP_WAIT(n)  asm volatile("cp.async.wait_group %0;\n" :: "n"(n))

__device__ __forceinline__ void ldsm4(uint32_t& r0, uint32_t& r1, uint32_t& r2,
                                      uint32_t& r3, uint32_t a) {
    asm volatile("ldmatrix.sync.aligned.m8n8.x4.shared.b16 {%0,%1,%2,%3}, [%4];\n"
                 : "=r"(r0), "=r"(r1), "=r"(r2), "=r"(r3) : "r"(a));
}
__device__ __forceinline__ void ldsm4t(uint32_t& r0, uint32_t& r1, uint32_t& r2,
                                       uint32_t& r3, uint32_t a) {
    asm volatile("ldmatrix.sync.aligned.m8n8.x4.trans.shared.b16 {%0,%1,%2,%3}, [%4];\n"
                 : "=r"(r0), "=r"(r1), "=r"(r2), "=r"(r3) : "r"(a));
}
__device__ __forceinline__ void mma16(float* c, const uint32_t* a, const uint32_t* b) {
    asm volatile(
        "mma.sync.aligned.m16n8k16.row.col.f32.f16.f16.f32 "
        "{%0,%1,%2,%3}, {%4,%5,%6,%7}, {%8,%9}, {%0,%1,%2,%3};\n"
        : "+f"(c[0]), "+f"(c[1]), "+f"(c[2]), "+f"(c[3])
        : "r"(a[0]), "r"(a[1]), "r"(a[2]), "r"(a[3]), "r"(b[0]), "r"(b[1]));
}
__device__ __forceinline__ uint32_t h2u(__half a, __half b) {
    __half2 t = __halves2half2(a, b);
    return *(uint32_t*)&t;
}
__device__ __forceinline__ float ex2(float x) {
    float r;
    asm("ex2.approx.ftz.f32 %0, %1;" : "=f"(r) : "f"(x));
    return r;
}

// ---------------- conversion kernels ----------------
__global__ void convx_k(const float* __restrict__ in, int n) {
    int i = (blockIdx.x * blockDim.x + threadIdx.x) << 2;
    if (i >= n) return;
    float4 v = *(const float4*)(in + i);
    *(__half2*)&g_xhi[i]     = __halves2half2(__float2half_rn(v.x), __float2half_rn(v.y));
    *(__half2*)&g_xhi[i + 2] = __halves2half2(__float2half_rn(v.z), __float2half_rn(v.w));
}
// all 4 weights in one launch: blockIdx.y selects which
__global__ void convw_k(const float* __restrict__ w0, const float* __restrict__ w1,
                        const float* __restrict__ w2, const float* __restrict__ w3,
                        int n, float s0) {
    int which = blockIdx.y;
    const float* in = (which == 0) ? w0 : (which == 1) ? w1 : (which == 2) ? w2 : w3;
    float scale = (which == 0) ? s0 : 1.0f;
    int i = (blockIdx.x * blockDim.x + threadIdx.x) << 2;
    if (i >= n) return;
    __half* hi = g_Whi + (size_t)which * ND * ND;
    __half* lo = g_Wlo + (size_t)which * ND * ND;
    float4 v = *(const float4*)(in + i);
    float f0 = v.x * scale, f1 = v.y * scale, f2 = v.z * scale, f3 = v.w * scale;
    __half h0 = __float2half_rn(f0), h1 = __float2half_rn(f1);
    __half h2 = __float2half_rn(f2), h3 = __float2half_rn(f3);
    *(__half2*)&hi[i]     = __halves2half2(h0, h1);
    *(__half2*)&hi[i + 2] = __halves2half2(h2, h3);
    *(__half2*)&lo[i]     = __halves2half2(__float2half_rn(f0 - __half2float(h0)),
                                           __float2half_rn(f1 - __half2float(h1)));
    *(__half2*)&lo[i + 2] = __halves2half2(__float2half_rn(f2 - __half2float(h2)),
                                           __float2half_rn(f3 - __half2float(h3)));
}

// =====================================================================
// QKV GEMM (fused, blockIdx.z = 0/1/2): 2-term, -> Q/K/V hi planes
// =====================================================================
#define SAH 24
#define GPLANE 3072
#define GBUFB 24576

__global__ __launch_bounds__(256) void qkv_k() {
    __shared__ __align__(16) __half sm[2 * 4 * GPLANE];

    const int tid = threadIdx.x, lane = tid & 31, wrp = tid >> 5;
    const int gid = lane >> 2, tq = lane & 3;
    const int wm = (wrp >> 2) * 64, wn = (wrp & 3) * 32;
    const int m0 = blockIdx.y * 128, n0 = blockIdx.x * 128;
    const int z = blockIdx.z;
    const uint32_t smb = s2u(sm);

    const __half* Wh = g_Whi + (size_t)z * ND * ND;
    const __half* Wl = g_Wlo + (size_t)z * ND * ND;

    const int lb = lane >> 3, lr = lane & 7;
    const uint32_t addrA0 = smb + ((wm + (lb & 1) * 8 + lr) * SAH + (lb >> 1) * 8) * 2;
    const uint32_t addrB0 = smb + 2 * GPLANE * 2 +
                            ((wn + (lane >> 4) * 8 + lr) * SAH + ((lane >> 3) & 1) * 8) * 2;

    const int rowc = tid >> 1, chc = (tid & 1) * 8;
    const uint32_t dA = smb + (rowc * SAH + chc) * 2;
    const uint32_t dB = smb + 2 * GPLANE * 2 + (rowc * SAH + chc) * 2;
    const __half* srcAh = g_xhi + (size_t)(m0 + rowc) * ND + chc;
    const __half* srcBh = Wh + (size_t)(n0 + rowc) * ND + chc;
    const __half* srcBl = Wl + (size_t)(n0 + rowc) * ND + chc;

    float acc[4][4][4];
#pragma unroll
    for (int i = 0; i < 4; i++)
#pragma unroll
        for (int j = 0; j < 4; j++)
#pragma unroll
            for (int e = 0; e < 4; e++) acc[i][j][e] = 0.f;

    auto issueAsync = [&](int kc, int buf) {
        uint32_t bo = buf * GBUFB;
        cpa16(dA + bo,              srcAh + kc);
        cpa16(dB + bo,              srcBh + kc);
        cpa16(dB + bo + GPLANE * 2, srcBl + kc);
    };
    auto compute = [&](int buf) {
        uint32_t bo = buf * GBUFB;
        uint32_t ah[4][4];
#pragma unroll
        for (int mi = 0; mi < 4; mi++)
            ldsm4(ah[mi][0], ah[mi][1], ah[mi][2], ah[mi][3],
                  addrA0 + bo + mi * 16 * SAH * 2);
        uint32_t bh[4][2], bl[4][2];
#pragma unroll
        for (int p = 0; p < 2; p++) {
            ldsm4(bh[2 * p][0], bh[2 * p][1], bh[2 * p + 1][0], bh[2 * p + 1][1],
                  addrB0 + bo + p * 16 * SAH * 2);
            ldsm4(bl[2 * p][0], bl[2 * p][1], bl[2 * p + 1][0], bl[2 * p + 1][1],
                  addrB0 + bo + GPLANE * 2 + p * 16 * SAH * 2);
        }
#pragma unroll
        for (int ni = 0; ni < 4; ni++)
#pragma unroll
            for (int mi = 0; mi < 4; mi++) {
                mma16(acc[mi][ni], ah[mi], bh[ni]);
                mma16(acc[mi][ni], ah[mi], bl[ni]);
            }
    };

    issueAsync(0, 0); CP_COMMIT();
    for (int c = 0; c < 64; c++) {
        if (c < 63) { issueAsync((c + 1) << 4, (c + 1) & 1); CP_COMMIT(); CP_WAIT(1); }
        else CP_WAIT(0);
        __syncthreads();
        compute(c & 1);
        __syncthreads();
    }

    __half* dh = (z == 0) ? g_Qh : (z == 1) ? g_KhG : g_VhG;
#pragma unroll
    for (int mi = 0; mi < 4; mi++)
#pragma unroll
        for (int ni = 0; ni < 4; ni++)
#pragma unroll
            for (int half_ = 0; half_ < 2; half_++) {
                int row = m0 + wm + mi * 16 + gid + half_ * 8;
                int col = n0 + wn + ni * 8 + tq * 2;
                float v0 = acc[mi][ni][half_ * 2];
                float v1 = acc[mi][ni][half_ * 2 + 1];
                int b = row >> 11, s = row & 2047, h = col >> 6, d = col & 63;
                size_t idx = (((size_t)(b * NHEAD + h)) * S_LEN + s) * HDIM + d;
                *(__half2*)&dh[idx] =
                    __halves2half2(__float2half_rn(v0), __float2half_rn(v1));
            }
}

// =====================================================================
// Wo GEMM: 3-term (A = O hi+lo planes) -> fp32 d_out + bias
// =====================================================================
__global__ __launch_bounds__(256) void gemmo_k(const float* __restrict__ bias,
                                               float* __restrict__ Cout) {
    __shared__ __align__(16) __half sm[2 * 4 * GPLANE];

    const int tid = threadIdx.x, lane = tid & 31, wrp = tid >> 5;
    const int gid = lane >> 2, tq = lane & 3;
    const int wm = (wrp >> 2) * 64, wn = (wrp & 3) * 32;
    const int m0 = blockIdx.y * 128, n0 = blockIdx.x * 128;
    const uint32_t smb = s2u(sm);

    const __half* Wh = g_Whi + (size_t)3 * ND * ND;
    const __half* Wl = g_Wlo + (size_t)3 * ND * ND;

    const int lb = lane >> 3, lr = lane & 7;
    const uint32_t addrA0 = smb + ((wm + (lb & 1) * 8 + lr) * SAH + (lb >> 1) * 8) * 2;
    const uint32_t addrB0 = smb + 2 * GPLANE * 2 +
                            ((wn + (lane >> 4) * 8 + lr) * SAH + ((lane >> 3) & 1) * 8) * 2;

    const int rowc = tid >> 1, chc = (tid & 1) * 8;
    const uint32_t dA = smb + (rowc * SAH + chc) * 2;
    const uint32_t dB = smb + 2 * GPLANE * 2 + (rowc * SAH + chc) * 2;
    const __half* srcAh = g_Ohi + (size_t)(m0 + rowc) * ND + chc;
    const __half* srcAl = g_Olo + (size_t)(m0 + rowc) * ND + chc;
    const __half* srcBh = Wh + (size_t)(n0 + rowc) * ND + chc;
    const __half* srcBl = Wl + (size_t)(n0 + rowc) * ND + chc;

    float acc[4][4][4];
#pragma unroll
    for (int i = 0; i < 4; i++)
#pragma unroll
        for (int j = 0; j < 4; j++)
#pragma unroll
            for (int e = 0; e < 4; e++) acc[i][j][e] = 0.f;

    auto issueAsync = [&](int kc, int buf) {
        uint32_t bo = buf * GBUFB;
        cpa16(dA + bo,              srcAh + kc);
        cpa16(dA + bo + GPLANE * 2, srcAl + kc);
        cpa16(dB + bo,              srcBh + kc);
        cpa16(dB + bo + GPLANE * 2, srcBl + kc);
    };
    auto compute = [&](int buf) {
        uint32_t bo = buf * GBUFB;
        uint32_t ah[4][4], al[4][4];
#pragma unroll
        for (int mi = 0; mi < 4; mi++) {
            ldsm4(ah[mi][0], ah[mi][1], ah[mi][2], ah[mi][3],
                  addrA0 + bo + mi * 16 * SAH * 2);
            ldsm4(al[mi][0], al[mi][1], al[mi][2], al[mi][3],
                  addrA0 + bo + GPLANE * 2 + mi * 16 * SAH * 2);
        }
        uint32_t bh[4][2], bl[4][2];
#pragma unroll
        for (int p = 0; p < 2; p++) {
            ldsm4(bh[2 * p][0], bh[2 * p][1], bh[2 * p + 1][0], bh[2 * p + 1][1],
                  addrB0 + bo + p * 16 * SAH * 2);
            ldsm4(bl[2 * p][0], bl[2 * p][1], bl[2 * p + 1][0], bl[2 * p + 1][1],
                  addrB0 + bo + GPLANE * 2 + p * 16 * SAH * 2);
        }
#pragma unroll
        for (int ni = 0; ni < 4; ni++)
#pragma unroll
            for (int mi = 0; mi < 4; mi++) {
                mma16(acc[mi][ni], ah[mi], bh[ni]);
                mma16(acc[mi][ni], ah[mi], bl[ni]);
                mma16(acc[mi][ni], al[mi], bh[ni]);
            }
    };

    issueAsync(0, 0); CP_COMMIT();
    for (int c = 0; c < 64; c++) {
        if (c < 63) { issueAsync((c + 1) << 4, (c + 1) & 1); CP_COMMIT(); CP_WAIT(1); }
        else CP_WAIT(0);
        __syncthreads();
        compute(c & 1);
        __syncthreads();
    }

#pragma unroll
    for (int mi = 0; mi < 4; mi++)
#pragma unroll
        for (int ni = 0; ni < 4; ni++)
#pragma unroll
            for (int half_ = 0; half_ < 2; half_++) {
                int row = m0 + wm + mi * 16 + gid + half_ * 8;
                int col = n0 + wn + ni * 8 + tq * 2;
                float v0 = acc[mi][ni][half_ * 2] + bias[col];
                float v1 = acc[mi][ni][half_ * 2 + 1] + bias[col + 1];
                *(float2*)(Cout + (size_t)row * ND + col) = make_float2(v0, v1);
            }
}

// =====================================================================
// Flash attention, max-free softmax (fixed offset M0=6 folded into QE).
// S = Q_hi K_hi, PV = P_hi V_hi. 128 q rows/CTA, 8 warps.
// =====================================================================
#define AKVB 18432
#define A_KH 0
#define A_VH 9216
#define QEW  66
#define ASMEM (2 * AKVB + 128 * QEW * 4)   // 70656

__global__ __launch_bounds__(256) void attn_k(const float* __restrict__ rel) {
    extern __shared__ char smraw[];
    float* QEs = (float*)(smraw + 2 * AKVB);
    __half* relh = (__half*)smraw;
    __half* rell = relh + 72 * 72;
    const uint32_t smb = s2u(smraw);

    const int tid = threadIdx.x, lane = tid & 31, w = tid >> 5;
    const int gid = lane >> 2, tq = lane & 3, wr = w * 16;
    const int q0 = blockIdx.x * 128;
    const int bh = blockIdx.y;
    const size_t kvbase = (size_t)bh * S_LEN * HDIM;

    for (int i = tid; i < 72 * 64; i += 256) {
        int v = i >> 6, d = i & 63;
        float rv = (v < NREL) ? rel[v * 64 + d] * 8.0f : 0.f;
        __half h = __float2half_rn(rv);
        relh[v * 72 + d] = h;
        rell[v * 72 + d] = __float2half_rn(rv - __half2float(h));
    }

    uint32_t qhi[4][4];
    {
        const size_t qb = ((size_t)bh * S_LEN + q0) * HDIM;
        const __half* qh = g_Qh + qb;
#pragma unroll
        for (int kc = 0; kc < 4; kc++) {
            int c0 = kc * 16 + 2 * tq;
            size_t r0 = (size_t)(wr + gid) * 64, r1 = (size_t)(wr + gid + 8) * 64;
            qhi[kc][0] = *(const uint32_t*)(qh + r0 + c0);
            qhi[kc][1] = *(const uint32_t*)(qh + r1 + c0);
            qhi[kc][2] = *(const uint32_t*)(qh + r0 + c0 + 8);
            qhi[kc][3] = *(const uint32_t*)(qh + r1 + c0 + 8);
        }
    }
    __syncthreads();

    // qe = Q_hi . rel^T  - M0   (fixed exp offset folded in)
#pragma unroll
    for (int ni = 0; ni < 9; ni++) {
        float qe[4] = {0.f, 0.f, 0.f, 0.f};
#pragma unroll
        for (int kc = 0; kc < 4; kc++) {
            int nb = (ni * 8 + gid) * 72 + kc * 16 + 2 * tq;
            uint32_t bh_[2], bl_[2];
            bh_[0] = *(const uint32_t*)&relh[nb];
            bh_[1] = *(const uint32_t*)&relh[nb + 8];
            bl_[0] = *(const uint32_t*)&rell[nb];
            bl_[1] = *(const uint32_t*)&rell[nb + 8];
            mma16(qe, qhi[kc], bh_);
            mma16(qe, qhi[kc], bl_);
        }
        int col = ni * 8 + 2 * tq;
        if (col < NREL) {
            QEs[(wr + gid) * QEW + col]     = qe[0] - 6.0f;
            QEs[(wr + gid + 8) * QEW + col] = qe[2] - 6.0f;
        }
        if (col + 1 < NREL) {
            QEs[(wr + gid) * QEW + col + 1]     = qe[1] - 6.0f;
            QEs[(wr + gid + 8) * QEW + col + 1] = qe[3] - 6.0f;
        }
    }
    __syncthreads();

    const int arow = tid >> 3, ach = (tid & 7) * 8;
    const uint32_t dstKV = smb + (arow * 72 + ach) * 2;
    auto issue = [&](int j, int buf) {
        uint32_t bo = buf * AKVB;
        size_t src0 = kvbase + (size_t)(j * 64 + arow) * 64 + ach;
        size_t src1 = src0 + 32 * 64;
        cpa16(dstKV + bo + A_KH, g_KhG + src0);
        cpa16(dstKV + bo + A_VH, g_VhG + src0);
        uint32_t d2 = dstKV + 32 * 72 * 2;
        cpa16(d2 + bo + A_KH, g_KhG + src1);
        cpa16(d2 + bo + A_VH, g_VhG + src1);
    };

    const int lr = lane & 7;
    const uint32_t kbase0 = smb + A_KH + (lr * 72 + (lane >> 3) * 8) * 2;
    const uint32_t vbase0 = smb + A_VH + (((lane >> 3) * 8 + lr) * 72) * 2;

    float o[8][4];
#pragma unroll
    for (int i = 0; i < 8; i++)
#pragma unroll
        for (int e = 0; e < 4; e++) o[i][e] = 0.f;
    float l0 = 0.f, l1 = 0.f;

    issue(0, 0); CP_COMMIT();

    for (int j = 0; j < 32; j++) {
        if (j < 31) { issue(j + 1, (j + 1) & 1); CP_COMMIT(); CP_WAIT(1); }
        else CP_WAIT(0);
        __syncthreads();
        const uint32_t bo = (j & 1) * AKVB;

        // ---- S = Q_hi K_hi^T ----
        float sc[8][4];
#pragma unroll
        for (int ni = 0; ni < 8; ni++)
#pragma unroll
            for (int e = 0; e < 4; e++) sc[ni][e] = 0.f;
#pragma unroll
        for (int ni = 0; ni < 8; ni++) {
#pragma unroll
            for (int kcp = 0; kcp < 2; kcp++) {
                uint32_t k0r, k1r, k2r, k3r;
                ldsm4(k0r, k1r, k2r, k3r,
                      kbase0 + bo + (ni * 576 + kcp * 32) * 2);
                uint32_t f01[2] = {k0r, k1r}, f23[2] = {k2r, k3r};
                mma16(sc[ni], qhi[2 * kcp], f01);
                mma16(sc[ni], qhi[2 * kcp + 1], f23);
            }
        }

        // ---- bias (carries -M0) + exp + accumulate l, pack P ----
        const int k0 = j * 64;
        uint32_t pAh[8][2];
#pragma unroll
        for (int ni = 0; ni < 8; ni++) {
#pragma unroll
            for (int e = 0; e < 4; e++) {
                int ql_ = wr + gid + ((e >> 1) << 3);
                int key = k0 + ni * 8 + (tq << 1) + (e & 1);
                int d2 = (q0 + ql_) - key;
                d2 = d2 < -32 ? -32 : (d2 > 32 ? 32 : d2);
                sc[ni][e] += QEs[ql_ * QEW + d2 + 32];
            }
            float p0 = ex2(sc[ni][0]);
            float p1 = ex2(sc[ni][1]);
            float p2 = ex2(sc[ni][2]);
            float p3 = ex2(sc[ni][3]);
            l0 += p0 + p1;
            l1 += p2 + p3;
            pAh[ni][0] = h2u(__float2half_rn(p0), __float2half_rn(p1));
            pAh[ni][1] = h2u(__float2half_rn(p2), __float2half_rn(p3));
        }

        // ---- O += P_hi V_hi ----
#pragma unroll
        for (int kcp = 0; kcp < 2; kcp++) {
            uint32_t a0[4] = {pAh[4 * kcp][0],     pAh[4 * kcp][1],
                              pAh[4 * kcp + 1][0], pAh[4 * kcp + 1][1]};
            uint32_t a1[4] = {pAh[4 * kcp + 2][0], pAh[4 * kcp + 2][1],
                              pAh[4 * kcp + 3][0], pAh[4 * kcp + 3][1]};
#pragma unroll
            for (int ni = 0; ni < 8; ni++) {
                uint32_t v0r, v1r, v2r, v3r;
                ldsm4t(v0r, v1r, v2r, v3r,
                       vbase0 + bo + (kcp * 2304 + ni * 8) * 2);
                uint32_t f01[2] = {v0r, v1r}, f23[2] = {v2r, v3r};
                mma16(o[ni], a0, f01);
                mma16(o[ni], a1, f23);
            }
        }
        __syncthreads();
    }

    // ---- final row-sum of l across the quad, normalize, write O planes ----
    l0 += __shfl_xor_sync(0xffffffffu, l0, 1);
    l0 += __shfl_xor_sync(0xffffffffu, l0, 2);
    l1 += __shfl_xor_sync(0xffffffffu, l1, 1);
    l1 += __shfl_xor_sync(0xffffffffu, l1, 2);
    float inv0 = 1.f / l0, inv1 = 1.f / l1;
    const int rowg = (bh >> 4) * S_LEN + q0;
    const int colh = (bh & 15) * 64;
#pragma unroll
    for (int ni = 0; ni < 8; ni++) {
        int col = colh + ni * 8 + (tq << 1);
        size_t r0 = (size_t)(rowg + wr + gid) * ND + col;
        size_t r1 = (size_t)(rowg + wr + gid + 8) * ND + col;
        float v0 = o[ni][0] * inv0, v1 = o[ni][1] * inv0;
        __half h0 = __float2half_rn(v0), h1 = __float2half_rn(v1);
        *(__half2*)&g_Ohi[r0] = __halves2half2(h0, h1);
        *(__half2*)&g_Olo[r0] = __halves2half2(__float2half_rn(v0 - __half2float(h0)),
                                               __float2half_rn(v1 - __half2float(h1)));
        float v2 = o[ni][2] * inv1, v3 = o[ni][3] * inv1;
        __half h2 = __float2half_rn(v2), h3 = __float2half_rn(v3);
        *(__half2*)&g_Ohi[r1] = __halves2half2(h2, h3);
        *(__half2*)&g_Olo[r1] = __halves2half2(__float2half_rn(v2 - __half2float(h2)),
                                               __float2half_rn(v3 - __half2float(h3)));
    }
}

// =====================================================================
extern "C" void kernel_launch(void* const* d_in, const int* in_sizes, int n_in,
                              void* d_out, int out_size) {
    (void)in_sizes; (void)n_in; (void)out_size;
    const float* x   = (const float*)d_in[0];
    const float* Wq  = (const float*)d_in[1];
    const float* Wk  = (const float*)d_in[2];
    const float* Wv  = (const float*)d_in[3];
    const float* Wo  = (const float*)d_in[4];
    const float* bo  = (const float*)d_in[5];
    const float* rel = (const float*)d_in[6];
    float* out = (float*)d_out;

    convx_k<<<NM * ND / 4 / 256, 256>>>(x, NM * ND);
    convw_k<<<dim3(ND * ND / 4 / 256, 4), 256>>>(Wq, Wk, Wv, Wo, ND * ND,
                                                 0.125f * 1.44269504088896f);

    qkv_k<<<dim3(ND / 128, NM / 128, 3), 256>>>();

    cudaFuncSetAttribute((const void*)attn_k,
                         cudaFuncAttributeMaxDynamicSharedMemorySize, ASMEM);
    attn_k<<<dim3(S_LEN / 128, NBH), 256, ASMEM>>>(rel);

    gemmo_k<<<dim3(ND / 128, NM / 128), 256>>>(bo, out);
}

// round 15
// speedup vs baseline: 1.0795x; 1.0795x over previous
#include <cuda_runtime.h>
#include <cuda_fp16.h>
#include <cstdint>

#define S_LEN 2048
#define NHEAD 16
#define HDIM  64
#define NREL  65
#define NBH   32
#define NM    4096
#define ND    1024

// ---------------- static device scratch ----------------
__device__ __half g_xhi[NM * ND];
__device__ __half g_Whi[4 * ND * ND], g_Wlo[4 * ND * ND];
__device__ __half g_Qh[NBH * S_LEN * HDIM];
__device__ __half g_KhG[NBH * S_LEN * HDIM];
__device__ __half g_VhG[NBH * S_LEN * HDIM];
__device__ __half g_Ohi[NM * ND], g_Olo[NM * ND];

// ---------------- helpers ----------------
__device__ __forceinline__ uint32_t s2u(const void* p) {
    return (uint32_t)__cvta_generic_to_shared(p);
}
__device__ __forceinline__ void cpa16(uint32_t d, const void* s) {
    asm volatile("cp.async.cg.shared.global [%0], [%1], 16;\n" :: "r"(d), "l"(s));
}
#define CP_COMMIT() asm volatile("cp.async.commit_group;\n" ::)
#define CP_WAIT(n)  asm volatile("cp.async.wait_group %0;\n" :: "n"(n))

__device__ __forceinline__ void ldsm4(uint32_t& r0, uint32_t& r1, uint32_t& r2,
                                      uint32_t& r3, uint32_t a) {
    asm volatile("ldmatrix.sync.aligned.m8n8.x4.shared.b16 {%0,%1,%2,%3}, [%4];\n"
                 : "=r"(r0), "=r"(r1), "=r"(r2), "=r"(r3) : "r"(a));
}
__device__ __forceinline__ void ldsm4t(uint32_t& r0, uint32_t& r1, uint32_t& r2,
                                       uint32_t& r3, uint32_t a) {
    asm volatile("ldmatrix.sync.aligned.m8n8.x4.trans.shared.b16 {%0,%1,%2,%3}, [%4];\n"
                 : "=r"(r0), "=r"(r1), "=r"(r2), "=r"(r3) : "r"(a));
}
__device__ __forceinline__ void mma16(float* c, const uint32_t* a, const uint32_t* b) {
    asm volatile(
        "mma.sync.aligned.m16n8k16.row.col.f32.f16.f16.f32 "
        "{%0,%1,%2,%3}, {%4,%5,%6,%7}, {%8,%9}, {%0,%1,%2,%3};\n"
        : "+f"(c[0]), "+f"(c[1]), "+f"(c[2]), "+f"(c[3])
        : "r"(a[0]), "r"(a[1]), "r"(a[2]), "r"(a[3]), "r"(b[0]), "r"(b[1]));
}
__device__ __forceinline__ uint32_t h2u(__half a, __half b) {
    __half2 t = __halves2half2(a, b);
    return *(uint32_t*)&t;
}
__device__ __forceinline__ float ex2(float x) {
    float r;
    asm("ex2.approx.ftz.f32 %0, %1;" : "=f"(r) : "f"(x));
    return r;
}

// ---------------- conversion kernels ----------------
__global__ void convx_k(const float* __restrict__ in, int n) {
    int i = (blockIdx.x * blockDim.x + threadIdx.x) << 2;
    if (i >= n) return;
    float4 v = *(const float4*)(in + i);
    *(__half2*)&g_xhi[i]     = __halves2half2(__float2half_rn(v.x), __float2half_rn(v.y));
    *(__half2*)&g_xhi[i + 2] = __halves2half2(__float2half_rn(v.z), __float2half_rn(v.w));
}
__global__ void convw_k(const float* __restrict__ w0, const float* __restrict__ w1,
                        const float* __restrict__ w2, const float* __restrict__ w3,
                        int n, float s0) {
    int which = blockIdx.y;
    const float* in = (which == 0) ? w0 : (which == 1) ? w1 : (which == 2) ? w2 : w3;
    float scale = (which == 0) ? s0 : 1.0f;
    int i = (blockIdx.x * blockDim.x + threadIdx.x) << 2;
    if (i >= n) return;
    __half* hi = g_Whi + (size_t)which * ND * ND;
    __half* lo = g_Wlo + (size_t)which * ND * ND;
    float4 v = *(const float4*)(in + i);
    float f0 = v.x * scale, f1 = v.y * scale, f2 = v.z * scale, f3 = v.w * scale;
    __half h0 = __float2half_rn(f0), h1 = __float2half_rn(f1);
    __half h2 = __float2half_rn(f2), h3 = __float2half_rn(f3);
    *(__half2*)&hi[i]     = __halves2half2(h0, h1);
    *(__half2*)&hi[i + 2] = __halves2half2(h2, h3);
    if (which == 3) {   // only Wo's lo plane is consumed
        *(__half2*)&lo[i]     = __halves2half2(__float2half_rn(f0 - __half2float(h0)),
                                               __float2half_rn(f1 - __half2float(h1)));
        *(__half2*)&lo[i + 2] = __halves2half2(__float2half_rn(f2 - __half2float(h2)),
                                               __float2half_rn(f3 - __half2float(h3)));
    }
}

// =====================================================================
// QKV GEMM (fused, blockIdx.z = 0/1/2): 1-term (x_hi * W_hi)
// =====================================================================
#define SAH 24
#define GPLANE 3072
#define GBUFB 24576

__global__ __launch_bounds__(256) void qkv_k() {
    __shared__ __align__(16) __half sm[2 * 4 * GPLANE];

    const int tid = threadIdx.x, lane = tid & 31, wrp = tid >> 5;
    const int gid = lane >> 2, tq = lane & 3;
    const int wm = (wrp >> 2) * 64, wn = (wrp & 3) * 32;
    const int m0 = blockIdx.y * 128, n0 = blockIdx.x * 128;
    const int z = blockIdx.z;
    const uint32_t smb = s2u(sm);

    const __half* Wh = g_Whi + (size_t)z * ND * ND;

    const int lb = lane >> 3, lr = lane & 7;
    const uint32_t addrA0 = smb + ((wm + (lb & 1) * 8 + lr) * SAH + (lb >> 1) * 8) * 2;
    const uint32_t addrB0 = smb + 2 * GPLANE * 2 +
                            ((wn + (lane >> 4) * 8 + lr) * SAH + ((lane >> 3) & 1) * 8) * 2;

    const int rowc = tid >> 1, chc = (tid & 1) * 8;
    const uint32_t dA = smb + (rowc * SAH + chc) * 2;
    const uint32_t dB = smb + 2 * GPLANE * 2 + (rowc * SAH + chc) * 2;
    const __half* srcAh = g_xhi + (size_t)(m0 + rowc) * ND + chc;
    const __half* srcBh = Wh + (size_t)(n0 + rowc) * ND + chc;

    float acc[4][4][4];
#pragma unroll
    for (int i = 0; i < 4; i++)
#pragma unroll
        for (int j = 0; j < 4; j++)
#pragma unroll
            for (int e = 0; e < 4; e++) acc[i][j][e] = 0.f;

    auto issueAsync = [&](int kc, int buf) {
        uint32_t bo = buf * GBUFB;
        cpa16(dA + bo, srcAh + kc);
        cpa16(dB + bo, srcBh + kc);
    };
    auto compute = [&](int buf) {
        uint32_t bo = buf * GBUFB;
        uint32_t ah[4][4];
#pragma unroll
        for (int mi = 0; mi < 4; mi++)
            ldsm4(ah[mi][0], ah[mi][1], ah[mi][2], ah[mi][3],
                  addrA0 + bo + mi * 16 * SAH * 2);
        uint32_t bh[4][2];
#pragma unroll
        for (int p = 0; p < 2; p++)
            ldsm4(bh[2 * p][0], bh[2 * p][1], bh[2 * p + 1][0], bh[2 * p + 1][1],
                  addrB0 + bo + p * 16 * SAH * 2);
#pragma unroll
        for (int ni = 0; ni < 4; ni++)
#pragma unroll
            for (int mi = 0; mi < 4; mi++)
                mma16(acc[mi][ni], ah[mi], bh[ni]);
    };

    issueAsync(0, 0); CP_COMMIT();
    for (int c = 0; c < 64; c++) {
        if (c < 63) { issueAsync((c + 1) << 4, (c + 1) & 1); CP_COMMIT(); CP_WAIT(1); }
        else CP_WAIT(0);
        __syncthreads();
        compute(c & 1);
        __syncthreads();
    }

    __half* dh = (z == 0) ? g_Qh : (z == 1) ? g_KhG : g_VhG;
#pragma unroll
    for (int mi = 0; mi < 4; mi++)
#pragma unroll
        for (int ni = 0; ni < 4; ni++)
#pragma unroll
            for (int half_ = 0; half_ < 2; half_++) {
                int row = m0 + wm + mi * 16 + gid + half_ * 8;
                int col = n0 + wn + ni * 8 + tq * 2;
                float v0 = acc[mi][ni][half_ * 2];
                float v1 = acc[mi][ni][half_ * 2 + 1];
                int b = row >> 11, s = row & 2047, h = col >> 6, d = col & 63;
                size_t idx = (((size_t)(b * NHEAD + h)) * S_LEN + s) * HDIM + d;
                *(__half2*)&dh[idx] =
                    __halves2half2(__float2half_rn(v0), __float2half_rn(v1));
            }
}

// =====================================================================
// Wo GEMM: 3-term (A = O hi+lo planes) -> fp32 d_out + bias
// =====================================================================
__global__ __launch_bounds__(256) void gemmo_k(const float* __restrict__ bias,
                                               float* __restrict__ Cout) {
    __shared__ __align__(16) __half sm[2 * 4 * GPLANE];

    const int tid = threadIdx.x, lane = tid & 31, wrp = tid >> 5;
    const int gid = lane >> 2, tq = lane & 3;
    const int wm = (wrp >> 2) * 64, wn = (wrp & 3) * 32;
    const int m0 = blockIdx.y * 128, n0 = blockIdx.x * 128;
    const uint32_t smb = s2u(sm);

    const __half* Wh = g_Whi + (size_t)3 * ND * ND;
    const __half* Wl = g_Wlo + (size_t)3 * ND * ND;

    const int lb = lane >> 3, lr = lane & 7;
    const uint32_t addrA0 = smb + ((wm + (lb & 1) * 8 + lr) * SAH + (lb >> 1) * 8) * 2;
    const uint32_t addrB0 = smb + 2 * GPLANE * 2 +
                            ((wn + (lane >> 4) * 8 + lr) * SAH + ((lane >> 3) & 1) * 8) * 2;

    const int rowc = tid >> 1, chc = (tid & 1) * 8;
    const uint32_t dA = smb + (rowc * SAH + chc) * 2;
    const uint32_t dB = smb + 2 * GPLANE * 2 + (rowc * SAH + chc) * 2;
    const __half* srcAh = g_Ohi + (size_t)(m0 + rowc) * ND + chc;
    const __half* srcAl = g_Olo + (size_t)(m0 + rowc) * ND + chc;
    const __half* srcBh = Wh + (size_t)(n0 + rowc) * ND + chc;
    const __half* srcBl = Wl + (size_t)(n0 + rowc) * ND + chc;

    float acc[4][4][4];
#pragma unroll
    for (int i = 0; i < 4; i++)
#pragma unroll
        for (int j = 0; j < 4; j++)
#pragma unroll
            for (int e = 0; e < 4; e++) acc[i][j][e] = 0.f;

    auto issueAsync = [&](int kc, int buf) {
        uint32_t bo = buf * GBUFB;
        cpa16(dA + bo,              srcAh + kc);
        cpa16(dA + bo + GPLANE * 2, srcAl + kc);
        cpa16(dB + bo,              srcBh + kc);
        cpa16(dB + bo + GPLANE * 2, srcBl + kc);
    };
    auto compute = [&](int buf) {
        uint32_t bo = buf * GBUFB;
        uint32_t ah[4][4], al[4][4];
#pragma unroll
        for (int mi = 0; mi < 4; mi++) {
            ldsm4(ah[mi][0], ah[mi][1], ah[mi][2], ah[mi][3],
                  addrA0 + bo + mi * 16 * SAH * 2);
            ldsm4(al[mi][0], al[mi][1], al[mi][2], al[mi][3],
                  addrA0 + bo + GPLANE * 2 + mi * 16 * SAH * 2);
        }
        uint32_t bh[4][2], bl[4][2];
#pragma unroll
        for (int p = 0; p < 2; p++) {
            ldsm4(bh[2 * p][0], bh[2 * p][1], bh[2 * p + 1][0], bh[2 * p + 1][1],
                  addrB0 + bo + p * 16 * SAH * 2);
            ldsm4(bl[2 * p][0], bl[2 * p][1], bl[2 * p + 1][0], bl[2 * p + 1][1],
                  addrB0 + bo + GPLANE * 2 + p * 16 * SAH * 2);
        }
#pragma unroll
        for (int ni = 0; ni < 4; ni++)
#pragma unroll
            for (int mi = 0; mi < 4; mi++) {
                mma16(acc[mi][ni], ah[mi], bh[ni]);
                mma16(acc[mi][ni], ah[mi], bl[ni]);
                mma16(acc[mi][ni], al[mi], bh[ni]);
            }
    };

    issueAsync(0, 0); CP_COMMIT();
    for (int c = 0; c < 64; c++) {
        if (c < 63) { issueAsync((c + 1) << 4, (c + 1) & 1); CP_COMMIT(); CP_WAIT(1); }
        else CP_WAIT(0);
        __syncthreads();
        compute(c & 1);
        __syncthreads();
    }

#pragma unroll
    for (int mi = 0; mi < 4; mi++)
#pragma unroll
        for (int ni = 0; ni < 4; ni++)
#pragma unroll
            for (int half_ = 0; half_ < 2; half_++) {
                int row = m0 + wm + mi * 16 + gid + half_ * 8;
                int col = n0 + wn + ni * 8 + tq * 2;
                float v0 = acc[mi][ni][half_ * 2] + bias[col];
                float v1 = acc[mi][ni][half_ * 2 + 1] + bias[col + 1];
                *(float2*)(Cout + (size_t)row * ND + col) = make_float2(v0, v1);
            }
}

// =====================================================================
// Flash attention, max-free softmax, saturated-bias fast path.
// S = Q_hi K_hi, PV = P_hi V_hi. 128 q rows/CTA, 8 warps.
// =====================================================================
#define AKVB 18432
#define A_KH 0
#define A_VH 9216
#define QEW  66
#define ASMEM (2 * AKVB + 128 * QEW * 4)   // 70656

__global__ __launch_bounds__(256) void attn_k(const float* __restrict__ rel) {
    extern __shared__ char smraw[];
    float* QEs = (float*)(smraw + 2 * AKVB);
    __half* relh = (__half*)smraw;
    __half* rell = relh + 72 * 72;
    const uint32_t smb = s2u(smraw);

    const int tid = threadIdx.x, lane = tid & 31, w = tid >> 5;
    const int gid = lane >> 2, tq = lane & 3, wr = w * 16;
    const int q0 = blockIdx.x * 128;
    const int bh = blockIdx.y;
    const size_t kvbase = (size_t)bh * S_LEN * HDIM;

    for (int i = tid; i < 72 * 64; i += 256) {
        int v = i >> 6, d = i & 63;
        float rv = (v < NREL) ? rel[v * 64 + d] * 8.0f : 0.f;
        __half h = __float2half_rn(rv);
        relh[v * 72 + d] = h;
        rell[v * 72 + d] = __float2half_rn(rv - __half2float(h));
    }

    uint32_t qhi[4][4];
    {
        const size_t qb = ((size_t)bh * S_LEN + q0) * HDIM;
        const __half* qh = g_Qh + qb;
#pragma unroll
        for (int kc = 0; kc < 4; kc++) {
            int c0 = kc * 16 + 2 * tq;
            size_t r0 = (size_t)(wr + gid) * 64, r1 = (size_t)(wr + gid + 8) * 64;
            qhi[kc][0] = *(const uint32_t*)(qh + r0 + c0);
            qhi[kc][1] = *(const uint32_t*)(qh + r1 + c0);
            qhi[kc][2] = *(const uint32_t*)(qh + r0 + c0 + 8);
            qhi[kc][3] = *(const uint32_t*)(qh + r1 + c0 + 8);
        }
    }
    __syncthreads();

    // qe = Q_hi . rel^T  - M0
#pragma unroll
    for (int ni = 0; ni < 9; ni++) {
        float qe[4] = {0.f, 0.f, 0.f, 0.f};
#pragma unroll
        for (int kc = 0; kc < 4; kc++) {
            int nb = (ni * 8 + gid) * 72 + kc * 16 + 2 * tq;
            uint32_t bh_[2], bl_[2];
            bh_[0] = *(const uint32_t*)&relh[nb];
            bh_[1] = *(const uint32_t*)&relh[nb + 8];
            bl_[0] = *(const uint32_t*)&rell[nb];
            bl_[1] = *(const uint32_t*)&rell[nb + 8];
            mma16(qe, qhi[kc], bh_);
            mma16(qe, qhi[kc], bl_);
        }
        int col = ni * 8 + 2 * tq;
        if (col < NREL) {
            QEs[(wr + gid) * QEW + col]     = qe[0] - 6.0f;
            QEs[(wr + gid + 8) * QEW + col] = qe[2] - 6.0f;
        }
        if (col + 1 < NREL) {
            QEs[(wr + gid) * QEW + col + 1]     = qe[1] - 6.0f;
            QEs[(wr + gid + 8) * QEW + col + 1] = qe[3] - 6.0f;
        }
    }
    __syncthreads();

    const int arow = tid >> 3, ach = (tid & 7) * 8;
    const uint32_t dstKV = smb + (arow * 72 + ach) * 2;
    auto issue = [&](int j, int buf) {
        uint32_t bo = buf * AKVB;
        size_t src0 = kvbase + (size_t)(j * 64 + arow) * 64 + ach;
        size_t src1 = src0 + 32 * 64;
        cpa16(dstKV + bo + A_KH, g_KhG + src0);
        cpa16(dstKV + bo + A_VH, g_VhG + src0);
        uint32_t d2 = dstKV + 32 * 72 * 2;
        cpa16(d2 + bo + A_KH, g_KhG + src1);
        cpa16(d2 + bo + A_VH, g_VhG + src1);
    };

    const int lr = lane & 7;
    const uint32_t kbase0 = smb + A_KH + (lr * 72 + (lane >> 3) * 8) * 2;
    const uint32_t vbase0 = smb + A_VH + (((lane >> 3) * 8 + lr) * 72) * 2;

    float o[8][4];
#pragma unroll
    for (int i = 0; i < 8; i++)
#pragma unroll
        for (int e = 0; e < 4; e++) o[i][e] = 0.f;
    float l0 = 0.f, l1 = 0.f;

    issue(0, 0); CP_COMMIT();

    for (int j = 0; j < 32; j++) {
        if (j < 31) { issue(j + 1, (j + 1) & 1); CP_COMMIT(); CP_WAIT(1); }
        else CP_WAIT(0);
        __syncthreads();
        const uint32_t bo = (j & 1) * AKVB;

        // ---- S = Q_hi K_hi^T ----
        float sc[8][4];
#pragma unroll
        for (int ni = 0; ni < 8; ni++)
#pragma unroll
            for (int e = 0; e < 4; e++) sc[ni][e] = 0.f;
#pragma unroll
        for (int ni = 0; ni < 8; ni++) {
#pragma unroll
            for (int kcp = 0; kcp < 2; kcp++) {
                uint32_t k0r, k1r, k2r, k3r;
                ldsm4(k0r, k1r, k2r, k3r,
                      kbase0 + bo + (ni * 576 + kcp * 32) * 2);
                uint32_t f01[2] = {k0r, k1r}, f23[2] = {k2r, k3r};
                mma16(sc[ni], qhi[2 * kcp], f01);
                mma16(sc[ni], qhi[2 * kcp + 1], f23);
            }
        }

        // ---- bias + exp + pack P ----
        const int k0 = j * 64;
        uint32_t pAh[8][2];
        if (k0 <= q0 - 95 || k0 >= q0 + 159) {
            // whole tile clip-saturated: per-row constant bias (broadcast LDS)
            const int idx = (k0 < q0) ? 64 : 0;
            const float b0 = QEs[(wr + gid) * QEW + idx];
            const float b1 = QEs[(wr + gid + 8) * QEW + idx];
#pragma unroll
            for (int ni = 0; ni < 8; ni++) {
                float p0 = ex2(sc[ni][0] + b0);
                float p1 = ex2(sc[ni][1] + b0);
                float p2 = ex2(sc[ni][2] + b1);
                float p3 = ex2(sc[ni][3] + b1);
                l0 += p0 + p1;
                l1 += p2 + p3;
                pAh[ni][0] = h2u(__float2half_rn(p0), __float2half_rn(p1));
                pAh[ni][1] = h2u(__float2half_rn(p2), __float2half_rn(p3));
            }
        } else {
#pragma unroll
            for (int ni = 0; ni < 8; ni++) {
#pragma unroll
                for (int e = 0; e < 4; e++) {
                    int ql_ = wr + gid + ((e >> 1) << 3);
                    int key = k0 + ni * 8 + (tq << 1) + (e & 1);
                    int d2 = (q0 + ql_) - key;
                    d2 = d2 < -32 ? -32 : (d2 > 32 ? 32 : d2);
                    sc[ni][e] += QEs[ql_ * QEW + d2 + 32];
                }
                float p0 = ex2(sc[ni][0]);
                float p1 = ex2(sc[ni][1]);
                float p2 = ex2(sc[ni][2]);
                float p3 = ex2(sc[ni][3]);
                l0 += p0 + p1;
                l1 += p2 + p3;
                pAh[ni][0] = h2u(__float2half_rn(p0), __float2half_rn(p1));
                pAh[ni][1] = h2u(__float2half_rn(p2), __float2half_rn(p3));
            }
        }

        // ---- O += P_hi V_hi ----
#pragma unroll
        for (int kcp = 0; kcp < 2; kcp++) {
            uint32_t a0[4] = {pAh[4 * kcp][0],     pAh[4 * kcp][1],
                              pAh[4 * kcp + 1][0], pAh[4 * kcp + 1][1]};
            uint32_t a1[4] = {pAh[4 * kcp + 2][0], pAh[4 * kcp + 2][1],
                              pAh[4 * kcp + 3][0], pAh[4 * kcp + 3][1]};
#pragma unroll
            for (int ni = 0; ni < 8; ni++) {
                uint32_t v0r, v1r, v2r, v3r;
                ldsm4t(v0r, v1r, v2r, v3r,
                       vbase0 + bo + (kcp * 2304 + ni * 8) * 2);
                uint32_t f01[2] = {v0r, v1r}, f23[2] = {v2r, v3r};
                mma16(o[ni], a0, f01);
                mma16(o[ni], a1, f23);
            }
        }
        __syncthreads();
    }

    // ---- final l reduction, normalize, write O planes ----
    l0 += __shfl_xor_sync(0xffffffffu, l0, 1);
    l0 += __shfl_xor_sync(0xffffffffu, l0, 2);
    l1 += __shfl_xor_sync(0xffffffffu, l1, 1);
    l1 += __shfl_xor_sync(0xffffffffu, l1, 2);
    float inv0 = 1.f / l0, inv1 = 1.f / l1;
    const int rowg = (bh >> 4) * S_LEN + q0;
    const int colh = (bh & 15) * 64;
#pragma unroll
    for (int ni = 0; ni < 8; ni++) {
        int col = colh + ni * 8 + (tq << 1);
        size_t r0 = (size_t)(rowg + wr + gid) * ND + col;
        size_t r1 = (size_t)(rowg + wr + gid + 8) * ND + col;
        float v0 = o[ni][0] * inv0, v1 = o[ni][1] * inv0;
        __half h0 = __float2half_rn(v0), h1 = __float2half_rn(v1);
        *(__half2*)&g_Ohi[r0] = __halves2half2(h0, h1);
        *(__half2*)&g_Olo[r0] = __halves2half2(__float2half_rn(v0 - __half2float(h0)),
                                               __float2half_rn(v1 - __half2float(h1)));
        float v2 = o[ni][2] * inv1, v3 = o[ni][3] * inv1;
        __half h2 = __float2half_rn(v2), h3 = __float2half_rn(v3);
        *(__half2*)&g_Ohi[r1] = __halves2half2(h2, h3);
        *(__half2*)&g_Olo[r1] = __halves2half2(__float2half_rn(v2 - __half2float(h2)),
                                               __float2half_rn(v3 - __half2float(h3)));
    }
}

// =====================================================================
extern "C" void kernel_launch(void* const* d_in, const int* in_sizes, int n_in,
                              void* d_out, int out_size) {
    (void)in_sizes; (void)n_in; (void)out_size;
    const float* x   = (const float*)d_in[0];
    const float* Wq  = (const float*)d_in[1];
    const float* Wk  = (const float*)d_in[2];
    const float* Wv  = (const float*)d_in[3];
    const float* Wo  = (const float*)d_in[4];
    const float* bo  = (const float*)d_in[5];
    const float* rel = (const float*)d_in[6];
    float* out = (float*)d_out;

    convx_k<<<NM * ND / 4 / 256, 256>>>(x, NM * ND);
    convw_k<<<dim3(ND * ND / 4 / 256, 4), 256>>>(Wq, Wk, Wv, Wo, ND * ND,
                                                 0.125f * 1.44269504088896f);

    qkv_k<<<dim3(ND / 128, NM / 128, 3), 256>>>();

    cudaFuncSetAttribute((const void*)attn_k,
                         cudaFuncAttributeMaxDynamicSharedMemorySize, ASMEM);
    attn_k<<<dim3(S_LEN / 128, NBH), 256, ASMEM>>>(rel);

    gemmo_k<<<dim3(ND / 128, NM / 128), 256>>>(bo, out);
}

// round 16
// speedup vs baseline: 1.1552x; 1.0701x over previous
#include <cuda_runtime.h>
#include <cuda_fp16.h>
#include <cstdint>

#define S_LEN 2048
#define NHEAD 16
#define HDIM  64
#define NREL  65
#define NBH   32
#define NM    4096
#define ND    1024

// ---------------- static device scratch ----------------
__device__ __half g_xhi[NM * ND];
__device__ __half g_Whi[4 * ND * ND], g_Wlo[4 * ND * ND];
__device__ __half g_Qh[NBH * S_LEN * HDIM];
__device__ __half g_KhG[NBH * S_LEN * HDIM];
__device__ __half g_VhG[NBH * S_LEN * HDIM];
__device__ __half g_Ohi[NM * ND], g_Olo[NM * ND];

// ---------------- helpers ----------------
__device__ __forceinline__ uint32_t s2u(const void* p) {
    return (uint32_t)__cvta_generic_to_shared(p);
}
__device__ __forceinline__ void cpa16(uint32_t d, const void* s) {
    asm volatile("cp.async.cg.shared.global [%0], [%1], 16;\n" :: "r"(d), "l"(s));
}
#define CP_COMMIT() asm volatile("cp.async.commit_group;\n" ::)
#define CP_WAIT(n)  asm volatile("cp.async.wait_group %0;\n" :: "n"(n))

__device__ __forceinline__ void ldsm4(uint32_t& r0, uint32_t& r1, uint32_t& r2,
                                      uint32_t& r3, uint32_t a) {
    asm volatile("ldmatrix.sync.aligned.m8n8.x4.shared.b16 {%0,%1,%2,%3}, [%4];\n"
                 : "=r"(r0), "=r"(r1), "=r"(r2), "=r"(r3) : "r"(a));
}
__device__ __forceinline__ void ldsm4t(uint32_t& r0, uint32_t& r1, uint32_t& r2,
                                       uint32_t& r3, uint32_t a) {
    asm volatile("ldmatrix.sync.aligned.m8n8.x4.trans.shared.b16 {%0,%1,%2,%3}, [%4];\n"
                 : "=r"(r0), "=r"(r1), "=r"(r2), "=r"(r3) : "r"(a));
}
__device__ __forceinline__ void mma16(float* c, const uint32_t* a, const uint32_t* b) {
    asm volatile(
        "mma.sync.aligned.m16n8k16.row.col.f32.f16.f16.f32 "
        "{%0,%1,%2,%3}, {%4,%5,%6,%7}, {%8,%9}, {%0,%1,%2,%3};\n"
        : "+f"(c[0]), "+f"(c[1]), "+f"(c[2]), "+f"(c[3])
        : "r"(a[0]), "r"(a[1]), "r"(a[2]), "r"(a[3]), "r"(b[0]), "r"(b[1]));
}
__device__ __forceinline__ uint32_t h2u(__half a, __half b) {
    __half2 t = __halves2half2(a, b);
    return *(uint32_t*)&t;
}
__device__ __forceinline__ float ex2(float x) {
    float r;
    asm("ex2.approx.ftz.f32 %0, %1;" : "=f"(r) : "f"(x));
    return r;
}

// ---------------- conversion kernels ----------------
__global__ void convx_k(const float* __restrict__ in, int n) {
    int i = (blockIdx.x * blockDim.x + threadIdx.x) << 2;
    if (i >= n) return;
    float4 v = *(const float4*)(in + i);
    *(__half2*)&g_xhi[i]     = __halves2half2(__float2half_rn(v.x), __float2half_rn(v.y));
    *(__half2*)&g_xhi[i + 2] = __halves2half2(__float2half_rn(v.z), __float2half_rn(v.w));
}
__global__ void convw_k(const float* __restrict__ w0, const float* __restrict__ w1,
                        const float* __restrict__ w2, const float* __restrict__ w3,
                        int n, float s0) {
    int which = blockIdx.y;
    const float* in = (which == 0) ? w0 : (which == 1) ? w1 : (which == 2) ? w2 : w3;
    float scale = (which == 0) ? s0 : 1.0f;
    int i = (blockIdx.x * blockDim.x + threadIdx.x) << 2;
    if (i >= n) return;
    __half* hi = g_Whi + (size_t)which * ND * ND;
    __half* lo = g_Wlo + (size_t)which * ND * ND;
    float4 v = *(const float4*)(in + i);
    float f0 = v.x * scale, f1 = v.y * scale, f2 = v.z * scale, f3 = v.w * scale;
    __half h0 = __float2half_rn(f0), h1 = __float2half_rn(f1);
    __half h2 = __float2half_rn(f2), h3 = __float2half_rn(f3);
    *(__half2*)&hi[i]     = __halves2half2(h0, h1);
    *(__half2*)&hi[i + 2] = __halves2half2(h2, h3);
    if (which == 3) {   // only Wo's lo plane is consumed
        *(__half2*)&lo[i]     = __halves2half2(__float2half_rn(f0 - __half2float(h0)),
                                               __float2half_rn(f1 - __half2float(h1)));
        *(__half2*)&lo[i + 2] = __halves2half2(__float2half_rn(f2 - __half2float(h2)),
                                               __float2half_rn(f3 - __half2float(h3)));
    }
}

// =====================================================================
// QKV GEMM (fused, blockIdx.z = 0/1/2): 1-term (x_hi * W_hi)
// =====================================================================
#define SAH 24
#define GPLANE 3072
#define GBUFB 24576

__global__ __launch_bounds__(256) void qkv_k() {
    __shared__ __align__(16) __half sm[2 * 4 * GPLANE];

    const int tid = threadIdx.x, lane = tid & 31, wrp = tid >> 5;
    const int gid = lane >> 2, tq = lane & 3;
    const int wm = (wrp >> 2) * 64, wn = (wrp & 3) * 32;
    const int m0 = blockIdx.y * 128, n0 = blockIdx.x * 128;
    const int z = blockIdx.z;
    const uint32_t smb = s2u(sm);

    const __half* Wh = g_Whi + (size_t)z * ND * ND;

    const int lb = lane >> 3, lr = lane & 7;
    const uint32_t addrA0 = smb + ((wm + (lb & 1) * 8 + lr) * SAH + (lb >> 1) * 8) * 2;
    const uint32_t addrB0 = smb + 2 * GPLANE * 2 +
                            ((wn + (lane >> 4) * 8 + lr) * SAH + ((lane >> 3) & 1) * 8) * 2;

    const int rowc = tid >> 1, chc = (tid & 1) * 8;
    const uint32_t dA = smb + (rowc * SAH + chc) * 2;
    const uint32_t dB = smb + 2 * GPLANE * 2 + (rowc * SAH + chc) * 2;
    const __half* srcAh = g_xhi + (size_t)(m0 + rowc) * ND + chc;
    const __half* srcBh = Wh + (size_t)(n0 + rowc) * ND + chc;

    float acc[4][4][4];
#pragma unroll
    for (int i = 0; i < 4; i++)
#pragma unroll
        for (int j = 0; j < 4; j++)
#pragma unroll
            for (int e = 0; e < 4; e++) acc[i][j][e] = 0.f;

    auto issueAsync = [&](int kc, int buf) {
        uint32_t bo = buf * GBUFB;
        cpa16(dA + bo, srcAh + kc);
        cpa16(dB + bo, srcBh + kc);
    };
    auto compute = [&](int buf) {
        uint32_t bo = buf * GBUFB;
        uint32_t ah[4][4];
#pragma unroll
        for (int mi = 0; mi < 4; mi++)
            ldsm4(ah[mi][0], ah[mi][1], ah[mi][2], ah[mi][3],
                  addrA0 + bo + mi * 16 * SAH * 2);
        uint32_t bh[4][2];
#pragma unroll
        for (int p = 0; p < 2; p++)
            ldsm4(bh[2 * p][0], bh[2 * p][1], bh[2 * p + 1][0], bh[2 * p + 1][1],
                  addrB0 + bo + p * 16 * SAH * 2);
#pragma unroll
        for (int ni = 0; ni < 4; ni++)
#pragma unroll
            for (int mi = 0; mi < 4; mi++)
                mma16(acc[mi][ni], ah[mi], bh[ni]);
    };

    issueAsync(0, 0); CP_COMMIT();
    for (int c = 0; c < 64; c++) {
        if (c < 63) { issueAsync((c + 1) << 4, (c + 1) & 1); CP_COMMIT(); CP_WAIT(1); }
        else CP_WAIT(0);
        __syncthreads();
        compute(c & 1);
        __syncthreads();
    }

    __half* dh = (z == 0) ? g_Qh : (z == 1) ? g_KhG : g_VhG;
#pragma unroll
    for (int mi = 0; mi < 4; mi++)
#pragma unroll
        for (int ni = 0; ni < 4; ni++)
#pragma unroll
            for (int half_ = 0; half_ < 2; half_++) {
                int row = m0 + wm + mi * 16 + gid + half_ * 8;
                int col = n0 + wn + ni * 8 + tq * 2;
                float v0 = acc[mi][ni][half_ * 2];
                float v1 = acc[mi][ni][half_ * 2 + 1];
                int b = row >> 11, s = row & 2047, h = col >> 6, d = col & 63;
                size_t idx = (((size_t)(b * NHEAD + h)) * S_LEN + s) * HDIM + d;
                *(__half2*)&dh[idx] =
                    __halves2half2(__float2half_rn(v0), __float2half_rn(v1));
            }
}

// =====================================================================
// Wo GEMM: 3-term (A = O hi+lo planes) -> fp32 d_out + bias
// =====================================================================
__global__ __launch_bounds__(256) void gemmo_k(const float* __restrict__ bias,
                                               float* __restrict__ Cout) {
    __shared__ __align__(16) __half sm[2 * 4 * GPLANE];

    const int tid = threadIdx.x, lane = tid & 31, wrp = tid >> 5;
    const int gid = lane >> 2, tq = lane & 3;
    const int wm = (wrp >> 2) * 64, wn = (wrp & 3) * 32;
    const int m0 = blockIdx.y * 128, n0 = blockIdx.x * 128;
    const uint32_t smb = s2u(sm);

    const __half* Wh = g_Whi + (size_t)3 * ND * ND;
    const __half* Wl = g_Wlo + (size_t)3 * ND * ND;

    const int lb = lane >> 3, lr = lane & 7;
    const uint32_t addrA0 = smb + ((wm + (lb & 1) * 8 + lr) * SAH + (lb >> 1) * 8) * 2;
    const uint32_t addrB0 = smb + 2 * GPLANE * 2 +
                            ((wn + (lane >> 4) * 8 + lr) * SAH + ((lane >> 3) & 1) * 8) * 2;

    const int rowc = tid >> 1, chc = (tid & 1) * 8;
    const uint32_t dA = smb + (rowc * SAH + chc) * 2;
    const uint32_t dB = smb + 2 * GPLANE * 2 + (rowc * SAH + chc) * 2;
    const __half* srcAh = g_Ohi + (size_t)(m0 + rowc) * ND + chc;
    const __half* srcAl = g_Olo + (size_t)(m0 + rowc) * ND + chc;
    const __half* srcBh = Wh + (size_t)(n0 + rowc) * ND + chc;
    const __half* srcBl = Wl + (size_t)(n0 + rowc) * ND + chc;

    float acc[4][4][4];
#pragma unroll
    for (int i = 0; i < 4; i++)
#pragma unroll
        for (int j = 0; j < 4; j++)
#pragma unroll
            for (int e = 0; e < 4; e++) acc[i][j][e] = 0.f;

    auto issueAsync = [&](int kc, int buf) {
        uint32_t bo = buf * GBUFB;
        cpa16(dA + bo,              srcAh + kc);
        cpa16(dA + bo + GPLANE * 2, srcAl + kc);
        cpa16(dB + bo,              srcBh + kc);
        cpa16(dB + bo + GPLANE * 2, srcBl + kc);
    };
    auto compute = [&](int buf) {
        uint32_t bo = buf * GBUFB;
        uint32_t ah[4][4], al[4][4];
#pragma unroll
        for (int mi = 0; mi < 4; mi++) {
            ldsm4(ah[mi][0], ah[mi][1], ah[mi][2], ah[mi][3],
                  addrA0 + bo + mi * 16 * SAH * 2);
            ldsm4(al[mi][0], al[mi][1], al[mi][2], al[mi][3],
                  addrA0 + bo + GPLANE * 2 + mi * 16 * SAH * 2);
        }
        uint32_t bh[4][2], bl[4][2];
#pragma unroll
        for (int p = 0; p < 2; p++) {
            ldsm4(bh[2 * p][0], bh[2 * p][1], bh[2 * p + 1][0], bh[2 * p + 1][1],
                  addrB0 + bo + p * 16 * SAH * 2);
            ldsm4(bl[2 * p][0], bl[2 * p][1], bl[2 * p + 1][0], bl[2 * p + 1][1],
                  addrB0 + bo + GPLANE * 2 + p * 16 * SAH * 2);
        }
#pragma unroll
        for (int ni = 0; ni < 4; ni++)
#pragma unroll
            for (int mi = 0; mi < 4; mi++) {
                mma16(acc[mi][ni], ah[mi], bh[ni]);
                mma16(acc[mi][ni], ah[mi], bl[ni]);
                mma16(acc[mi][ni], al[mi], bh[ni]);
            }
    };

    issueAsync(0, 0); CP_COMMIT();
    for (int c = 0; c < 64; c++) {
        if (c < 63) { issueAsync((c + 1) << 4, (c + 1) & 1); CP_COMMIT(); CP_WAIT(1); }
        else CP_WAIT(0);
        __syncthreads();
        compute(c & 1);
        __syncthreads();
    }

#pragma unroll
    for (int mi = 0; mi < 4; mi++)
#pragma unroll
        for (int ni = 0; ni < 4; ni++)
#pragma unroll
            for (int half_ = 0; half_ < 2; half_++) {
                int row = m0 + wm + mi * 16 + gid + half_ * 8;
                int col = n0 + wn + ni * 8 + tq * 2;
                float v0 = acc[mi][ni][half_ * 2] + bias[col];
                float v1 = acc[mi][ni][half_ * 2 + 1] + bias[col + 1];
                *(float2*)(Cout + (size_t)row * ND + col) = make_float2(v0, v1);
            }
}

// =====================================================================
// Flash attention, max-free softmax, saturated-bias fast path.
// Bias arms only touch sc; shared exp/pack. min 2 CTAs/SM enforced.
// =====================================================================
#define AKVB 18432
#define A_KH 0
#define A_VH 9216
#define QEW  66
#define ASMEM (2 * AKVB + 128 * QEW * 4)   // 70656

__global__ __launch_bounds__(256, 2) void attn_k(const float* __restrict__ rel) {
    extern __shared__ char smraw[];
    float* QEs = (float*)(smraw + 2 * AKVB);
    __half* relh = (__half*)smraw;
    __half* rell = relh + 72 * 72;
    const uint32_t smb = s2u(smraw);

    const int tid = threadIdx.x, lane = tid & 31, w = tid >> 5;
    const int gid = lane >> 2, tq = lane & 3, wr = w * 16;
    const int q0 = blockIdx.x * 128;
    const int bh = blockIdx.y;
    const size_t kvbase = (size_t)bh * S_LEN * HDIM;

    for (int i = tid; i < 72 * 64; i += 256) {
        int v = i >> 6, d = i & 63;
        float rv = (v < NREL) ? rel[v * 64 + d] * 8.0f : 0.f;
        __half h = __float2half_rn(rv);
        relh[v * 72 + d] = h;
        rell[v * 72 + d] = __float2half_rn(rv - __half2float(h));
    }

    uint32_t qhi[4][4];
    {
        const size_t qb = ((size_t)bh * S_LEN + q0) * HDIM;
        const __half* qh = g_Qh + qb;
#pragma unroll
        for (int kc = 0; kc < 4; kc++) {
            int c0 = kc * 16 + 2 * tq;
            size_t r0 = (size_t)(wr + gid) * 64, r1 = (size_t)(wr + gid + 8) * 64;
            qhi[kc][0] = *(const uint32_t*)(qh + r0 + c0);
            qhi[kc][1] = *(const uint32_t*)(qh + r1 + c0);
            qhi[kc][2] = *(const uint32_t*)(qh + r0 + c0 + 8);
            qhi[kc][3] = *(const uint32_t*)(qh + r1 + c0 + 8);
        }
    }
    __syncthreads();

    // qe = Q_hi . rel^T  - M0
#pragma unroll
    for (int ni = 0; ni < 9; ni++) {
        float qe[4] = {0.f, 0.f, 0.f, 0.f};
#pragma unroll
        for (int kc = 0; kc < 4; kc++) {
            int nb = (ni * 8 + gid) * 72 + kc * 16 + 2 * tq;
            uint32_t bh_[2], bl_[2];
            bh_[0] = *(const uint32_t*)&relh[nb];
            bh_[1] = *(const uint32_t*)&relh[nb + 8];
            bl_[0] = *(const uint32_t*)&rell[nb];
            bl_[1] = *(const uint32_t*)&rell[nb + 8];
            mma16(qe, qhi[kc], bh_);
            mma16(qe, qhi[kc], bl_);
        }
        int col = ni * 8 + 2 * tq;
        if (col < NREL) {
            QEs[(wr + gid) * QEW + col]     = qe[0] - 6.0f;
            QEs[(wr + gid + 8) * QEW + col] = qe[2] - 6.0f;
        }
        if (col + 1 < NREL) {
            QEs[(wr + gid) * QEW + col + 1]     = qe[1] - 6.0f;
            QEs[(wr + gid + 8) * QEW + col + 1] = qe[3] - 6.0f;
        }
    }
    __syncthreads();

    const int arow = tid >> 3, ach = (tid & 7) * 8;
    const uint32_t dstKV = smb + (arow * 72 + ach) * 2;
    auto issue = [&](int j, int buf) {
        uint32_t bo = buf * AKVB;
        size_t src0 = kvbase + (size_t)(j * 64 + arow) * 64 + ach;
        size_t src1 = src0 + 32 * 64;
        cpa16(dstKV + bo + A_KH, g_KhG + src0);
        cpa16(dstKV + bo + A_VH, g_VhG + src0);
        uint32_t d2 = dstKV + 32 * 72 * 2;
        cpa16(d2 + bo + A_KH, g_KhG + src1);
        cpa16(d2 + bo + A_VH, g_VhG + src1);
    };

    const int lr = lane & 7;
    const uint32_t kbase0 = smb + A_KH + (lr * 72 + (lane >> 3) * 8) * 2;
    const uint32_t vbase0 = smb + A_VH + (((lane >> 3) * 8 + lr) * 72) * 2;

    float o[8][4];
#pragma unroll
    for (int i = 0; i < 8; i++)
#pragma unroll
        for (int e = 0; e < 4; e++) o[i][e] = 0.f;
    float l0 = 0.f, l1 = 0.f;

    issue(0, 0); CP_COMMIT();

    for (int j = 0; j < 32; j++) {
        if (j < 31) { issue(j + 1, (j + 1) & 1); CP_COMMIT(); CP_WAIT(1); }
        else CP_WAIT(0);
        __syncthreads();
        const uint32_t bo = (j & 1) * AKVB;

        // ---- S = Q_hi K_hi^T ----
        float sc[8][4];
#pragma unroll
        for (int ni = 0; ni < 8; ni++)
#pragma unroll
            for (int e = 0; e < 4; e++) sc[ni][e] = 0.f;
#pragma unroll
        for (int ni = 0; ni < 8; ni++) {
#pragma unroll
            for (int kcp = 0; kcp < 2; kcp++) {
                uint32_t k0r, k1r, k2r, k3r;
                ldsm4(k0r, k1r, k2r, k3r,
                      kbase0 + bo + (ni * 576 + kcp * 32) * 2);
                uint32_t f01[2] = {k0r, k1r}, f23[2] = {k2r, k3r};
                mma16(sc[ni], qhi[2 * kcp], f01);
                mma16(sc[ni], qhi[2 * kcp + 1], f23);
            }
        }

        // ---- bias into sc (arms write only sc; shared exp/pack below) ----
        const int k0 = j * 64;
        if (k0 <= q0 - 95 || k0 >= q0 + 159) {
            const int idx = (k0 < q0) ? 64 : 0;
            const float b0 = QEs[(wr + gid) * QEW + idx];
            const float b1 = QEs[(wr + gid + 8) * QEW + idx];
#pragma unroll
            for (int ni = 0; ni < 8; ni++) {
                sc[ni][0] += b0;
                sc[ni][1] += b0;
                sc[ni][2] += b1;
                sc[ni][3] += b1;
            }
        } else {
#pragma unroll
            for (int ni = 0; ni < 8; ni++)
#pragma unroll
                for (int e = 0; e < 4; e++) {
                    int ql_ = wr + gid + ((e >> 1) << 3);
                    int key = k0 + ni * 8 + (tq << 1) + (e & 1);
                    int d2 = (q0 + ql_) - key;
                    d2 = d2 < -32 ? -32 : (d2 > 32 ? 32 : d2);
                    sc[ni][e] += QEs[ql_ * QEW + d2 + 32];
                }
        }

        // ---- shared: exp + accumulate l + pack P ----
        uint32_t pAh[8][2];
#pragma unroll
        for (int ni = 0; ni < 8; ni++) {
            float p0 = ex2(sc[ni][0]);
            float p1 = ex2(sc[ni][1]);
            float p2 = ex2(sc[ni][2]);
            float p3 = ex2(sc[ni][3]);
            l0 += p0 + p1;
            l1 += p2 + p3;
            pAh[ni][0] = h2u(__float2half_rn(p0), __float2half_rn(p1));
            pAh[ni][1] = h2u(__float2half_rn(p2), __float2half_rn(p3));
        }

        // ---- O += P_hi V_hi ----
#pragma unroll
        for (int kcp = 0; kcp < 2; kcp++) {
            uint32_t a0[4] = {pAh[4 * kcp][0],     pAh[4 * kcp][1],
                              pAh[4 * kcp + 1][0], pAh[4 * kcp + 1][1]};
            uint32_t a1[4] = {pAh[4 * kcp + 2][0], pAh[4 * kcp + 2][1],
                              pAh[4 * kcp + 3][0], pAh[4 * kcp + 3][1]};
#pragma unroll
            for (int ni = 0; ni < 8; ni++) {
                uint32_t v0r, v1r, v2r, v3r;
                ldsm4t(v0r, v1r, v2r, v3r,
                       vbase0 + bo + (kcp * 2304 + ni * 8) * 2);
                uint32_t f01[2] = {v0r, v1r}, f23[2] = {v2r, v3r};
                mma16(o[ni], a0, f01);
                mma16(o[ni], a1, f23);
            }
        }
        __syncthreads();
    }

    // ---- final l reduction, normalize, write O planes ----
    l0 += __shfl_xor_sync(0xffffffffu, l0, 1);
    l0 += __shfl_xor_sync(0xffffffffu, l0, 2);
    l1 += __shfl_xor_sync(0xffffffffu, l1, 1);
    l1 += __shfl_xor_sync(0xffffffffu, l1, 2);
    float inv0 = 1.f / l0, inv1 = 1.f / l1;
    const int rowg = (bh >> 4) * S_LEN + q0;
    const int colh = (bh & 15) * 64;
#pragma unroll
    for (int ni = 0; ni < 8; ni++) {
        int col = colh + ni * 8 + (tq << 1);
        size_t r0 = (size_t)(rowg + wr + gid) * ND + col;
        size_t r1 = (size_t)(rowg + wr + gid + 8) * ND + col;
        float v0 = o[ni][0] * inv0, v1 = o[ni][1] * inv0;
        __half h0 = __float2half_rn(v0), h1 = __float2half_rn(v1);
        *(__half2*)&g_Ohi[r0] = __halves2half2(h0, h1);
        *(__half2*)&g_Olo[r0] = __halves2half2(__float2half_rn(v0 - __half2float(h0)),
                                               __float2half_rn(v1 - __half2float(h1)));
        float v2 = o[ni][2] * inv1, v3 = o[ni][3] * inv1;
        __half h2 = __float2half_rn(v2), h3 = __float2half_rn(v3);
        *(__half2*)&g_Ohi[r1] = __halves2half2(h2, h3);
        *(__half2*)&g_Olo[r1] = __halves2half2(__float2half_rn(v2 - __half2float(h2)),
                                               __float2half_rn(v3 - __half2float(h3)));
    }
}

// =====================================================================
extern "C" void kernel_launch(void* const* d_in, const int* in_sizes, int n_in,
                              void* d_out, int out_size) {
    (void)in_sizes; (void)n_in; (void)out_size;
    const float* x   = (const float*)d_in[0];
    const float* Wq  = (const float*)d_in[1];
    const float* Wk  = (const float*)d_in[2];
    const float* Wv  = (const float*)d_in[3];
    const float* Wo  = (const float*)d_in[4];
    const float* bo  = (const float*)d_in[5];
    const float* rel = (const float*)d_in[6];
    float* out = (float*)d_out;

    convx_k<<<NM * ND / 4 / 256, 256>>>(x, NM * ND);
    convw_k<<<dim3(ND * ND / 4 / 256, 4), 256>>>(Wq, Wk, Wv, Wo, ND * ND,
                                                 0.125f * 1.44269504088896f);

    qkv_k<<<dim3(ND / 128, NM / 128, 3), 256>>>();

    cudaFuncSetAttribute((const void*)attn_k,
                         cudaFuncAttributeMaxDynamicSharedMemorySize, ASMEM);
    attn_k<<<dim3(S_LEN / 128, NBH), 256, ASMEM>>>(rel);

    gemmo_k<<<dim3(ND / 128, NM / 128), 256>>>(bo, out);
}

// round 17
// speedup vs baseline: 1.2849x; 1.1124x over previous
#include <cuda_runtime.h>
#include <cuda_fp16.h>
#include <cstdint>

#define S_LEN 2048
#define NHEAD 16
#define HDIM  64
#define NREL  65
#define NBH   32
#define NM    4096
#define ND    1024

// ---------------- static device scratch ----------------
__device__ __half g_xhi[NM * ND];
__device__ __half g_Whi[4 * ND * ND], g_Wlo[4 * ND * ND];
__device__ __half g_Qh[NBH * S_LEN * HDIM];
__device__ __half g_KhG[NBH * S_LEN * HDIM];
__device__ __half g_VhG[NBH * S_LEN * HDIM];
__device__ __half g_Ohi[NM * ND];

// ---------------- helpers ----------------
__device__ __forceinline__ uint32_t s2u(const void* p) {
    return (uint32_t)__cvta_generic_to_shared(p);
}
__device__ __forceinline__ void cpa16(uint32_t d, const void* s) {
    asm volatile("cp.async.cg.shared.global [%0], [%1], 16;\n" :: "r"(d), "l"(s));
}
#define CP_COMMIT() asm volatile("cp.async.commit_group;\n" ::)
#define CP_WAIT(n)  asm volatile("cp.async.wait_group %0;\n" :: "n"(n))

__device__ __forceinline__ void ldsm4(uint32_t& r0, uint32_t& r1, uint32_t& r2,
                                      uint32_t& r3, uint32_t a) {
    asm volatile("ldmatrix.sync.aligned.m8n8.x4.shared.b16 {%0,%1,%2,%3}, [%4];\n"
                 : "=r"(r0), "=r"(r1), "=r"(r2), "=r"(r3) : "r"(a));
}
__device__ __forceinline__ void ldsm4t(uint32_t& r0, uint32_t& r1, uint32_t& r2,
                                       uint32_t& r3, uint32_t a) {
    asm volatile("ldmatrix.sync.aligned.m8n8.x4.trans.shared.b16 {%0,%1,%2,%3}, [%4];\n"
                 : "=r"(r0), "=r"(r1), "=r"(r2), "=r"(r3) : "r"(a));
}
__device__ __forceinline__ void mma16(float* c, const uint32_t* a, const uint32_t* b) {
    asm volatile(
        "mma.sync.aligned.m16n8k16.row.col.f32.f16.f16.f32 "
        "{%0,%1,%2,%3}, {%4,%5,%6,%7}, {%8,%9}, {%0,%1,%2,%3};\n"
        : "+f"(c[0]), "+f"(c[1]), "+f"(c[2]), "+f"(c[3])
        : "r"(a[0]), "r"(a[1]), "r"(a[2]), "r"(a[3]), "r"(b[0]), "r"(b[1]));
}
// pack (lo,hi) floats into one f16x2 register in a single cvt
__device__ __forceinline__ uint32_t f2h2(float lo, float hi) {
    uint32_t r;
    asm("cvt.rn.f16x2.f32 %0, %1, %2;" : "=r"(r) : "f"(hi), "f"(lo));
    return r;
}
__device__ __forceinline__ float ex2(float x) {
    float r;
    asm("ex2.approx.ftz.f32 %0, %1;" : "=f"(r) : "f"(x));
    return r;
}

// ---------------- conversion kernels ----------------
__global__ void convx_k(const float* __restrict__ in, int n) {
    int i = (blockIdx.x * blockDim.x + threadIdx.x) << 2;
    if (i >= n) return;
    float4 v = *(const float4*)(in + i);
    *(uint32_t*)&g_xhi[i]     = f2h2(v.x, v.y);
    *(uint32_t*)&g_xhi[i + 2] = f2h2(v.z, v.w);
}
__global__ void convw_k(const float* __restrict__ w0, const float* __restrict__ w1,
                        const float* __restrict__ w2, const float* __restrict__ w3,
                        int n, float s0) {
    int which = blockIdx.y;
    const float* in = (which == 0) ? w0 : (which == 1) ? w1 : (which == 2) ? w2 : w3;
    float scale = (which == 0) ? s0 : 1.0f;
    int i = (blockIdx.x * blockDim.x + threadIdx.x) << 2;
    if (i >= n) return;
    __half* hi = g_Whi + (size_t)which * ND * ND;
    __half* lo = g_Wlo + (size_t)which * ND * ND;
    float4 v = *(const float4*)(in + i);
    float f0 = v.x * scale, f1 = v.y * scale, f2 = v.z * scale, f3 = v.w * scale;
    __half h0 = __float2half_rn(f0), h1 = __float2half_rn(f1);
    __half h2 = __float2half_rn(f2), h3 = __float2half_rn(f3);
    *(__half2*)&hi[i]     = __halves2half2(h0, h1);
    *(__half2*)&hi[i + 2] = __halves2half2(h2, h3);
    if (which == 3) {   // only Wo's lo plane is consumed
        *(__half2*)&lo[i]     = __halves2half2(__float2half_rn(f0 - __half2float(h0)),
                                               __float2half_rn(f1 - __half2float(h1)));
        *(__half2*)&lo[i + 2] = __halves2half2(__float2half_rn(f2 - __half2float(h2)),
                                               __float2half_rn(f3 - __half2float(h3)));
    }
}

// =====================================================================
// QKV GEMM (fused, blockIdx.z = 0/1/2): 1-term (x_hi * W_hi)
// =====================================================================
#define SAH 24
#define GPLANE 3072
#define GBUFB 24576

__global__ __launch_bounds__(256) void qkv_k() {
    __shared__ __align__(16) __half sm[2 * 4 * GPLANE];

    const int tid = threadIdx.x, lane = tid & 31, wrp = tid >> 5;
    const int gid = lane >> 2, tq = lane & 3;
    const int wm = (wrp >> 2) * 64, wn = (wrp & 3) * 32;
    const int m0 = blockIdx.y * 128, n0 = blockIdx.x * 128;
    const int z = blockIdx.z;
    const uint32_t smb = s2u(sm);

    const __half* Wh = g_Whi + (size_t)z * ND * ND;

    const int lb = lane >> 3, lr = lane & 7;
    const uint32_t addrA0 = smb + ((wm + (lb & 1) * 8 + lr) * SAH + (lb >> 1) * 8) * 2;
    const uint32_t addrB0 = smb + 2 * GPLANE * 2 +
                            ((wn + (lane >> 4) * 8 + lr) * SAH + ((lane >> 3) & 1) * 8) * 2;

    const int rowc = tid >> 1, chc = (tid & 1) * 8;
    const uint32_t dA = smb + (rowc * SAH + chc) * 2;
    const uint32_t dB = smb + 2 * GPLANE * 2 + (rowc * SAH + chc) * 2;
    const __half* srcAh = g_xhi + (size_t)(m0 + rowc) * ND + chc;
    const __half* srcBh = Wh + (size_t)(n0 + rowc) * ND + chc;

    float acc[4][4][4];
#pragma unroll
    for (int i = 0; i < 4; i++)
#pragma unroll
        for (int j = 0; j < 4; j++)
#pragma unroll
            for (int e = 0; e < 4; e++) acc[i][j][e] = 0.f;

    auto issueAsync = [&](int kc, int buf) {
        uint32_t bo = buf * GBUFB;
        cpa16(dA + bo, srcAh + kc);
        cpa16(dB + bo, srcBh + kc);
    };
    auto compute = [&](int buf) {
        uint32_t bo = buf * GBUFB;
        uint32_t ah[4][4];
#pragma unroll
        for (int mi = 0; mi < 4; mi++)
            ldsm4(ah[mi][0], ah[mi][1], ah[mi][2], ah[mi][3],
                  addrA0 + bo + mi * 16 * SAH * 2);
        uint32_t bh[4][2];
#pragma unroll
        for (int p = 0; p < 2; p++)
            ldsm4(bh[2 * p][0], bh[2 * p][1], bh[2 * p + 1][0], bh[2 * p + 1][1],
                  addrB0 + bo + p * 16 * SAH * 2);
#pragma unroll
        for (int ni = 0; ni < 4; ni++)
#pragma unroll
            for (int mi = 0; mi < 4; mi++)
                mma16(acc[mi][ni], ah[mi], bh[ni]);
    };

    issueAsync(0, 0); CP_COMMIT();
    for (int c = 0; c < 64; c++) {
        if (c < 63) { issueAsync((c + 1) << 4, (c + 1) & 1); CP_COMMIT(); CP_WAIT(1); }
        else CP_WAIT(0);
        __syncthreads();
        compute(c & 1);
        __syncthreads();
    }

    __half* dh = (z == 0) ? g_Qh : (z == 1) ? g_KhG : g_VhG;
#pragma unroll
    for (int mi = 0; mi < 4; mi++)
#pragma unroll
        for (int ni = 0; ni < 4; ni++)
#pragma unroll
            for (int half_ = 0; half_ < 2; half_++) {
                int row = m0 + wm + mi * 16 + gid + half_ * 8;
                int col = n0 + wn + ni * 8 + tq * 2;
                float v0 = acc[mi][ni][half_ * 2];
                float v1 = acc[mi][ni][half_ * 2 + 1];
                int b = row >> 11, s = row & 2047, h = col >> 6, d = col & 63;
                size_t idx = (((size_t)(b * NHEAD + h)) * S_LEN + s) * HDIM + d;
                *(uint32_t*)&dh[idx] = f2h2(v0, v1);
            }
}

// =====================================================================
// Wo GEMM: 2-term (A = O_hi; W hi+lo) -> fp32 d_out + bias
// =====================================================================
__global__ __launch_bounds__(256) void gemmo_k(const float* __restrict__ bias,
                                               float* __restrict__ Cout) {
    __shared__ __align__(16) __half sm[2 * 4 * GPLANE];

    const int tid = threadIdx.x, lane = tid & 31, wrp = tid >> 5;
    const int gid = lane >> 2, tq = lane & 3;
    const int wm = (wrp >> 2) * 64, wn = (wrp & 3) * 32;
    const int m0 = blockIdx.y * 128, n0 = blockIdx.x * 128;
    const uint32_t smb = s2u(sm);

    const __half* Wh = g_Whi + (size_t)3 * ND * ND;
    const __half* Wl = g_Wlo + (size_t)3 * ND * ND;

    const int lb = lane >> 3, lr = lane & 7;
    const uint32_t addrA0 = smb + ((wm + (lb & 1) * 8 + lr) * SAH + (lb >> 1) * 8) * 2;
    const uint32_t addrB0 = smb + 2 * GPLANE * 2 +
                            ((wn + (lane >> 4) * 8 + lr) * SAH + ((lane >> 3) & 1) * 8) * 2;

    const int rowc = tid >> 1, chc = (tid & 1) * 8;
    const uint32_t dA = smb + (rowc * SAH + chc) * 2;
    const uint32_t dB = smb + 2 * GPLANE * 2 + (rowc * SAH + chc) * 2;
    const __half* srcAh = g_Ohi + (size_t)(m0 + rowc) * ND + chc;
    const __half* srcBh = Wh + (size_t)(n0 + rowc) * ND + chc;
    const __half* srcBl = Wl + (size_t)(n0 + rowc) * ND + chc;

    float acc[4][4][4];
#pragma unroll
    for (int i = 0; i < 4; i++)
#pragma unroll
        for (int j = 0; j < 4; j++)
#pragma unroll
            for (int e = 0; e < 4; e++) acc[i][j][e] = 0.f;

    auto issueAsync = [&](int kc, int buf) {
        uint32_t bo = buf * GBUFB;
        cpa16(dA + bo,              srcAh + kc);
        cpa16(dB + bo,              srcBh + kc);
        cpa16(dB + bo + GPLANE * 2, srcBl + kc);
    };
    auto compute = [&](int buf) {
        uint32_t bo = buf * GBUFB;
        uint32_t ah[4][4];
#pragma unroll
        for (int mi = 0; mi < 4; mi++)
            ldsm4(ah[mi][0], ah[mi][1], ah[mi][2], ah[mi][3],
                  addrA0 + bo + mi * 16 * SAH * 2);
        uint32_t bh[4][2], bl[4][2];
#pragma unroll
        for (int p = 0; p < 2; p++) {
            ldsm4(bh[2 * p][0], bh[2 * p][1], bh[2 * p + 1][0], bh[2 * p + 1][1],
                  addrB0 + bo + p * 16 * SAH * 2);
            ldsm4(bl[2 * p][0], bl[2 * p][1], bl[2 * p + 1][0], bl[2 * p + 1][1],
                  addrB0 + bo + GPLANE * 2 + p * 16 * SAH * 2);
        }
#pragma unroll
        for (int ni = 0; ni < 4; ni++)
#pragma unroll
            for (int mi = 0; mi < 4; mi++) {
                mma16(acc[mi][ni], ah[mi], bh[ni]);
                mma16(acc[mi][ni], ah[mi], bl[ni]);
            }
    };

    issueAsync(0, 0); CP_COMMIT();
    for (int c = 0; c < 64; c++) {
        if (c < 63) { issueAsync((c + 1) << 4, (c + 1) & 1); CP_COMMIT(); CP_WAIT(1); }
        else CP_WAIT(0);
        __syncthreads();
        compute(c & 1);
        __syncthreads();
    }

#pragma unroll
    for (int mi = 0; mi < 4; mi++)
#pragma unroll
        for (int ni = 0; ni < 4; ni++)
#pragma unroll
            for (int half_ = 0; half_ < 2; half_++) {
                int row = m0 + wm + mi * 16 + gid + half_ * 8;
                int col = n0 + wn + ni * 8 + tq * 2;
                float v0 = acc[mi][ni][half_ * 2] + bias[col];
                float v1 = acc[mi][ni][half_ * 2 + 1] + bias[col + 1];
                *(float2*)(Cout + (size_t)row * ND + col) = make_float2(v0, v1);
            }
}

// =====================================================================
// Flash attention: max-free softmax, saturated-bias fast path,
// l via ones-column tensor mma, f16x2 packed conversion.
// =====================================================================
#define AKVB 18432
#define A_KH 0
#define A_VH 9216
#define QEW  66
#define ASMEM (2 * AKVB + 128 * QEW * 4)   // 70656
#define ONES2 0x3C003C00u                   // half2(1.0, 1.0)

__global__ __launch_bounds__(256, 2) void attn_k(const float* __restrict__ rel) {
    extern __shared__ char smraw[];
    float* QEs = (float*)(smraw + 2 * AKVB);
    __half* relh = (__half*)smraw;
    __half* rell = relh + 72 * 72;
    const uint32_t smb = s2u(smraw);

    const int tid = threadIdx.x, lane = tid & 31, w = tid >> 5;
    const int gid = lane >> 2, tq = lane & 3, wr = w * 16;
    const int q0 = blockIdx.x * 128;
    const int bh = blockIdx.y;
    const size_t kvbase = (size_t)bh * S_LEN * HDIM;

    for (int i = tid; i < 72 * 64; i += 256) {
        int v = i >> 6, d = i & 63;
        float rv = (v < NREL) ? rel[v * 64 + d] * 8.0f : 0.f;
        __half h = __float2half_rn(rv);
        relh[v * 72 + d] = h;
        rell[v * 72 + d] = __float2half_rn(rv - __half2float(h));
    }

    uint32_t qhi[4][4];
    {
        const size_t qb = ((size_t)bh * S_LEN + q0) * HDIM;
        const __half* qh = g_Qh + qb;
#pragma unroll
        for (int kc = 0; kc < 4; kc++) {
            int c0 = kc * 16 + 2 * tq;
            size_t r0 = (size_t)(wr + gid) * 64, r1 = (size_t)(wr + gid + 8) * 64;
            qhi[kc][0] = *(const uint32_t*)(qh + r0 + c0);
            qhi[kc][1] = *(const uint32_t*)(qh + r1 + c0);
            qhi[kc][2] = *(const uint32_t*)(qh + r0 + c0 + 8);
            qhi[kc][3] = *(const uint32_t*)(qh + r1 + c0 + 8);
        }
    }
    __syncthreads();

    // qe = Q_hi . rel^T  - M0
#pragma unroll
    for (int ni = 0; ni < 9; ni++) {
        float qe[4] = {0.f, 0.f, 0.f, 0.f};
#pragma unroll
        for (int kc = 0; kc < 4; kc++) {
            int nb = (ni * 8 + gid) * 72 + kc * 16 + 2 * tq;
            uint32_t bh_[2], bl_[2];
            bh_[0] = *(const uint32_t*)&relh[nb];
            bh_[1] = *(const uint32_t*)&relh[nb + 8];
            bl_[0] = *(const uint32_t*)&rell[nb];
            bl_[1] = *(const uint32_t*)&rell[nb + 8];
            mma16(qe, qhi[kc], bh_);
            mma16(qe, qhi[kc], bl_);
        }
        int col = ni * 8 + 2 * tq;
        if (col < NREL) {
            QEs[(wr + gid) * QEW + col]     = qe[0] - 6.0f;
            QEs[(wr + gid + 8) * QEW + col] = qe[2] - 6.0f;
        }
        if (col + 1 < NREL) {
            QEs[(wr + gid) * QEW + col + 1]     = qe[1] - 6.0f;
            QEs[(wr + gid + 8) * QEW + col + 1] = qe[3] - 6.0f;
        }
    }
    __syncthreads();

    const int arow = tid >> 3, ach = (tid & 7) * 8;
    const uint32_t dstKV = smb + (arow * 72 + ach) * 2;
    auto issue = [&](int j, int buf) {
        uint32_t bo = buf * AKVB;
        size_t src0 = kvbase + (size_t)(j * 64 + arow) * 64 + ach;
        size_t src1 = src0 + 32 * 64;
        cpa16(dstKV + bo + A_KH, g_KhG + src0);
        cpa16(dstKV + bo + A_VH, g_VhG + src0);
        uint32_t d2 = dstKV + 32 * 72 * 2;
        cpa16(d2 + bo + A_KH, g_KhG + src1);
        cpa16(d2 + bo + A_VH, g_VhG + src1);
    };

    const int lr = lane & 7;
    const uint32_t kbase0 = smb + A_KH + (lr * 72 + (lane >> 3) * 8) * 2;
    const uint32_t vbase0 = smb + A_VH + (((lane >> 3) * 8 + lr) * 72) * 2;

    float o[8][4];
#pragma unroll
    for (int i = 0; i < 8; i++)
#pragma unroll
        for (int e = 0; e < 4; e++) o[i][e] = 0.f;
    float lsum[4] = {0.f, 0.f, 0.f, 0.f};
    const uint32_t onesf[2] = {ONES2, ONES2};

    issue(0, 0); CP_COMMIT();

    for (int j = 0; j < 32; j++) {
        if (j < 31) { issue(j + 1, (j + 1) & 1); CP_COMMIT(); CP_WAIT(1); }
        else CP_WAIT(0);
        __syncthreads();
        const uint32_t bo = (j & 1) * AKVB;

        // ---- S = Q_hi K_hi^T ----
        float sc[8][4];
#pragma unroll
        for (int ni = 0; ni < 8; ni++)
#pragma unroll
            for (int e = 0; e < 4; e++) sc[ni][e] = 0.f;
#pragma unroll
        for (int ni = 0; ni < 8; ni++) {
#pragma unroll
            for (int kcp = 0; kcp < 2; kcp++) {
                uint32_t k0r, k1r, k2r, k3r;
                ldsm4(k0r, k1r, k2r, k3r,
                      kbase0 + bo + (ni * 576 + kcp * 32) * 2);
                uint32_t f01[2] = {k0r, k1r}, f23[2] = {k2r, k3r};
                mma16(sc[ni], qhi[2 * kcp], f01);
                mma16(sc[ni], qhi[2 * kcp + 1], f23);
            }
        }

        // ---- bias into sc ----
        const int k0 = j * 64;
        if (k0 <= q0 - 95 || k0 >= q0 + 159) {
            const int idx = (k0 < q0) ? 64 : 0;
            const float b0 = QEs[(wr + gid) * QEW + idx];
            const float b1 = QEs[(wr + gid + 8) * QEW + idx];
#pragma unroll
            for (int ni = 0; ni < 8; ni++) {
                sc[ni][0] += b0;
                sc[ni][1] += b0;
                sc[ni][2] += b1;
                sc[ni][3] += b1;
            }
        } else {
#pragma unroll
            for (int ni = 0; ni < 8; ni++)
#pragma unroll
                for (int e = 0; e < 4; e++) {
                    int ql_ = wr + gid + ((e >> 1) << 3);
                    int key = k0 + ni * 8 + (tq << 1) + (e & 1);
                    int d2 = (q0 + ql_) - key;
                    d2 = d2 < -32 ? -32 : (d2 > 32 ? 32 : d2);
                    sc[ni][e] += QEs[ql_ * QEW + d2 + 32];
                }
        }

        // ---- exp + packed convert (l comes from tensor mma below) ----
        uint32_t pAh[8][2];
#pragma unroll
        for (int ni = 0; ni < 8; ni++) {
            pAh[ni][0] = f2h2(ex2(sc[ni][0]), ex2(sc[ni][1]));
            pAh[ni][1] = f2h2(ex2(sc[ni][2]), ex2(sc[ni][3]));
        }

        // ---- O += P_hi V_hi ; lsum += P_hi * ones ----
#pragma unroll
        for (int kcp = 0; kcp < 2; kcp++) {
            uint32_t a0[4] = {pAh[4 * kcp][0],     pAh[4 * kcp][1],
                              pAh[4 * kcp + 1][0], pAh[4 * kcp + 1][1]};
            uint32_t a1[4] = {pAh[4 * kcp + 2][0], pAh[4 * kcp + 2][1],
                              pAh[4 * kcp + 3][0], pAh[4 * kcp + 3][1]};
#pragma unroll
            for (int ni = 0; ni < 8; ni++) {
                uint32_t v0r, v1r, v2r, v3r;
                ldsm4t(v0r, v1r, v2r, v3r,
                       vbase0 + bo + (kcp * 2304 + ni * 8) * 2);
                uint32_t f01[2] = {v0r, v1r}, f23[2] = {v2r, v3r};
                mma16(o[ni], a0, f01);
                mma16(o[ni], a1, f23);
            }
            mma16(lsum, a0, onesf);
            mma16(lsum, a1, onesf);
        }
        __syncthreads();
    }

    // ---- normalize + write O (fp16 hi plane only) ----
    float inv0 = 1.f / lsum[0], inv1 = 1.f / lsum[2];
    const int rowg = (bh >> 4) * S_LEN + q0;
    const int colh = (bh & 15) * 64;
#pragma unroll
    for (int ni = 0; ni < 8; ni++) {
        int col = colh + ni * 8 + (tq << 1);
        size_t r0 = (size_t)(rowg + wr + gid) * ND + col;
        size_t r1 = (size_t)(rowg + wr + gid + 8) * ND + col;
        *(uint32_t*)&g_Ohi[r0] = f2h2(o[ni][0] * inv0, o[ni][1] * inv0);
        *(uint32_t*)&g_Ohi[r1] = f2h2(o[ni][2] * inv1, o[ni][3] * inv1);
    }
}

// =====================================================================
extern "C" void kernel_launch(void* const* d_in, const int* in_sizes, int n_in,
                              void* d_out, int out_size) {
    (void)in_sizes; (void)n_in; (void)out_size;
    const float* x   = (const float*)d_in[0];
    const float* Wq  = (const float*)d_in[1];
    const float* Wk  = (const float*)d_in[2];
    const float* Wv  = (const float*)d_in[3];
    const float* Wo  = (const float*)d_in[4];
    const float* bo  = (const float*)d_in[5];
    const float* rel = (const float*)d_in[6];
    float* out = (float*)d_out;

    convx_k<<<NM * ND / 4 / 256, 256>>>(x, NM * ND);
    convw_k<<<dim3(ND * ND / 4 / 256, 4), 256>>>(Wq, Wk, Wv, Wo, ND * ND,
                                                 0.125f * 1.44269504088896f);

    qkv_k<<<dim3(ND / 128, NM / 128, 3), 256>>>();

    cudaFuncSetAttribute((const void*)attn_k,
                         cudaFuncAttributeMaxDynamicSharedMemorySize, ASMEM);
    attn_k<<<dim3(S_LEN / 128, NBH), 256, ASMEM>>>(rel);

    gemmo_k<<<dim3(ND / 128, NM / 128), 256>>>(bo, out);
}